// round 14
// baseline (speedup 1.0000x reference)
#include <cuda_runtime.h>
#include <cuda_bf16.h>
#include <stdint.h>

#define DEV __device__ __forceinline__

// ---------------- problem constants ----------------
#define FEAT_B 2
#define FEAT_C 256
#define FEAT_H 100
#define FEAT_W 136
#define NROI   1000
#define KDIM   12544      // 256*49; bin-major layout: k' = bin*256 + c
#define HID    1024
#define SPLITK 3
#define CLAMP_LOG 4.1351665567423560f   // ln(1000/16)
#define IMG_W_ 1088.0f
#define IMG_H_ 800.0f

// fused work kernel block ranges (roi || trW1 || trW2)
#define F_ROI_BLOCKS NROI                            // 1000
#define F_W1_BLOCKS  ((HID / 32) * (KDIM / 32))      // 12544
#define F_W2_BLOCKS  ((HID / 32) * (HID / 32))       // 1024
#define F_TOTAL      (F_ROI_BLOCKS + F_W1_BLOCKS + F_W2_BLOCKS)

// ---------------- scratch (device globals; no allocation allowed) --------
__device__ float         g_featT[FEAT_B * FEAT_H * FEAT_W * FEAT_C]; // channels-last
__device__ __nv_bfloat16 g_fA_hi[NROI * KDIM];
__device__ __nv_bfloat16 g_fA_lo[NROI * KDIM];
__device__ __nv_bfloat16 g_w1t_hi[HID * KDIM];
__device__ __nv_bfloat16 g_w1t_lo[HID * KDIM];
__device__ __nv_bfloat16 g_w2t_hi[HID * HID];
__device__ __nv_bfloat16 g_w2t_lo[HID * HID];
__device__ __nv_bfloat16 g_h1_hi[NROI * HID];
__device__ __nv_bfloat16 g_h1_lo[NROI * HID];
__device__ float         g_part[SPLITK * NROI * HID];   // split-K partials
__device__ int           g_ticket[8 * 16];              // per-(m,n)-tile arrival count

// ---------------- helpers ----------------
DEV uint32_t smem_u32(const void* p) {
    uint32_t a;
    asm("{ .reg .u64 t; cvta.to.shared.u64 t, %1; cvt.u32.u64 %0, t; }" : "=r"(a) : "l"(p));
    return a;
}
DEV void cp_async16(uint32_t dst, const void* src, uint32_t src_size) {
    asm volatile("cp.async.cg.shared.global [%0], [%1], 16, %2;"
                 :: "r"(dst), "l"(src), "r"(src_size) : "memory");
}
DEV void cp_commit() { asm volatile("cp.async.commit_group;" ::: "memory"); }
template <int N>
DEV void cp_wait() { asm volatile("cp.async.wait_group %0;" :: "n"(N) : "memory"); }

DEV void ldm_x4(uint32_t* r, uint32_t addr) {
    asm volatile("ldmatrix.sync.aligned.m8n8.x4.shared.b16 {%0,%1,%2,%3}, [%4];"
                 : "=r"(r[0]), "=r"(r[1]), "=r"(r[2]), "=r"(r[3]) : "r"(addr));
}
DEV void mma16816(float* c, const uint32_t* a, const uint32_t* b) {
    asm volatile(
        "mma.sync.aligned.m16n8k16.row.col.f32.bf16.bf16.f32 "
        "{%0,%1,%2,%3}, {%4,%5,%6,%7}, {%8,%9}, {%0,%1,%2,%3};"
        : "+f"(c[0]), "+f"(c[1]), "+f"(c[2]), "+f"(c[3])
        : "r"(a[0]), "r"(a[1]), "r"(a[2]), "r"(a[3]), "r"(b[0]), "r"(b[1]));
}
DEV void split_bf16(float v, __nv_bfloat16& hi, __nv_bfloat16& lo) {
    hi = __float2bfloat16(v);
    lo = __float2bfloat16(v - __bfloat162float(hi));
}
// 64B-row XOR swizzle: 16B chunk index c in row r -> c ^ ((r>>1)&3)
DEV uint32_t swz(uint32_t row, uint32_t chunk) {
    return row * 64u + ((chunk ^ ((row >> 1) & 3u)) << 4);
}

// ================= feature transpose to channels-last =================
__global__ __launch_bounds__(256)
void featT_kernel(const float* __restrict__ feat, float* __restrict__ featT)
{
    __shared__ float tile[32][33];
    const int b  = blockIdx.z >> 3;
    const int cb = blockIdx.z & 7;
    const int h  = blockIdx.y;
    const int w0 = blockIdx.x * 32;
    const int tx = threadIdx.x, ty = threadIdx.y;

    const float* src = feat + ((size_t)b * FEAT_C + cb * 32) * (FEAT_H * FEAT_W)
                            + (size_t)h * FEAT_W;
    #pragma unroll
    for (int i = 0; i < 4; ++i) {
        const int w = w0 + tx;
        if (w < FEAT_W)
            tile[ty + i * 8][tx] = src[(size_t)(ty + i * 8) * (FEAT_H * FEAT_W) + w];
    }
    __syncthreads();
    float* dst = featT + ((size_t)(b * FEAT_H + h) * FEAT_W) * FEAT_C + cb * 32;
    #pragma unroll
    for (int i = 0; i < 4; ++i) {
        const int w = w0 + ty + i * 8;
        if (w < FEAT_W)
            dst[(size_t)w * FEAT_C + tx] = tile[tx][ty + i * 8];
    }
}

// ================= device pieces for fused work kernel =================
// ROI align v4 (bin-major, direct coalesced stores)
DEV void roi_align_dev(const float* __restrict__ featT,
                       const float* __restrict__ boxes,
                       const int*   __restrict__ rbatch,
                       __nv_bfloat16* __restrict__ out_hi,
                       __nv_bfloat16* __restrict__ out_lo,
                       int r, int t)
{
    const int half = t >> 7;
    const int c0 = (t & 127) * 2;

    __shared__ float sly[14], slx[14];
    __shared__ int   siy0[14], siy1[14], six0c[14], six1c[14];
    __shared__ float box4[4];
    __shared__ int   sb;

    if (t < 4) box4[t] = boxes[r * 4 + t];
    if (t == 4) sb = rbatch[r];
    __syncthreads();

    const float x1 = box4[0] * 0.125f, y1v = box4[1] * 0.125f;
    const float x2 = box4[2] * 0.125f, y2v = box4[3] * 0.125f;
    const float rw = fmaxf(x2 - x1, 1.0f);
    const float rh = fmaxf(y2v - y1v, 1.0f);
    const float bw = rw * (1.0f / 7.0f);
    const float bh = rh * (1.0f / 7.0f);

    if (t < 28) {
        const int p = t % 14;
        const float off = (float)(p >> 1) + ((float)(p & 1) + 0.5f) * 0.5f;
        if (t < 14) {
            float y = y1v + off * bh;
            y = fminf(fmaxf(y, 0.0f), (float)(FEAT_H - 1));
            float y0 = floorf(y);
            int y0i = (int)y0;
            siy0[p] = y0i;
            siy1[p] = min(y0i + 1, FEAT_H - 1);
            sly[p] = y - y0;
        } else {
            float x = x1 + off * bw;
            x = fminf(fmaxf(x, 0.0f), (float)(FEAT_W - 1));
            float x0 = floorf(x);
            int x0i = (int)x0;
            six0c[p] = x0i * FEAT_C;
            six1c[p] = min(x0i + 1, FEAT_W - 1) * FEAT_C;
            slx[p] = x - x0;
        }
    }
    __syncthreads();

    const float* fb = featT + (size_t)sb * (FEAT_H * FEAT_W * FEAT_C) + c0;
    __nv_bfloat16* gh = out_hi + (size_t)r * KDIM + c0;
    __nv_bfloat16* gl = out_lo + (size_t)r * KDIM + c0;

    const int byBeg = half ? 4 : 0;
    const int byEnd = half ? 7 : 4;

    #pragma unroll 1
    for (int by = byBeg; by < byEnd; ++by) {
        float accx[7], accy[7];
        #pragma unroll
        for (int j = 0; j < 7; ++j) { accx[j] = 0.0f; accy[j] = 0.0f; }

        #pragma unroll
        for (int sy = 0; sy < 2; ++sy) {
            const int py = by * 2 + sy;
            const float ly = sly[py];
            const float* r0 = fb + (size_t)(siy0[py] * FEAT_W) * FEAT_C;
            const float* r1 = fb + (size_t)(siy1[py] * FEAT_W) * FEAT_C;
            #pragma unroll
            for (int px = 0; px < 14; ++px) {
                const int x0c = six0c[px], x1c = six1c[px];
                const float lx = slx[px];
                const float2 v00 = *(const float2*)(r0 + x0c);
                const float2 v01 = *(const float2*)(r0 + x1c);
                const float2 v10 = *(const float2*)(r1 + x0c);
                const float2 v11 = *(const float2*)(r1 + x1c);
                const float topx = v00.x + (v01.x - v00.x) * lx;
                const float botx = v10.x + (v11.x - v10.x) * lx;
                const float topy = v00.y + (v01.y - v00.y) * lx;
                const float boty = v10.y + (v11.y - v10.y) * lx;
                accx[px >> 1] += topx + (botx - topx) * ly;
                accy[px >> 1] += topy + (boty - topy) * ly;
            }
        }
        #pragma unroll
        for (int bx = 0; bx < 7; ++bx) {
            const int bin = by * 7 + bx;
            __nv_bfloat16 hx, lxo, hy, lyo;
            split_bf16(accx[bx] * 0.25f, hx, lxo);
            split_bf16(accy[bx] * 0.25f, hy, lyo);
            __nv_bfloat162 hv; hv.x = hx; hv.y = hy;
            __nv_bfloat162 lv; lv.x = lxo; lv.y = lyo;
            *(__nv_bfloat162*)(gh + bin * 256) = hv;
            *(__nv_bfloat162*)(gl + bin * 256) = lv;
        }
    }
}

// transpose Wsrc[K][N] -> Wdst[N][K'] bf16 hi/lo. REORDER => bin-major perm.
template <bool REORDER>
DEV void transpose_dev(float tile[32][33],
                       const float* __restrict__ Wsrc,
                       __nv_bfloat16* __restrict__ Whi,
                       __nv_bfloat16* __restrict__ Wlo,
                       int K, int N, int n0, int k0, int t)
{
    const int tx = t & 31, ty = t >> 5;
    #pragma unroll
    for (int i = 0; i < 4; ++i) {
        const int kp = k0 + ty + i * 8;
        const int ksrc = REORDER ? ((kp & 255) * 49 + (kp >> 8)) : kp;
        tile[ty + i * 8][tx] = Wsrc[(size_t)ksrc * N + n0 + tx];
    }
    __syncthreads();
    #pragma unroll
    for (int it = 0; it < 2; ++it) {
        const int item = t + it * 256;        // 0..511 over (n, kpair)
        const int n = item >> 4;
        const int kp = item & 15;
        const float v0 = tile[kp * 2][n];
        const float v1 = tile[kp * 2 + 1][n];
        __nv_bfloat16 h0, l0, h1, l1;
        split_bf16(v0, h0, l0);
        split_bf16(v1, h1, l1);
        __nv_bfloat162 hv; hv.x = h0; hv.y = h1;
        __nv_bfloat162 lv; lv.x = l0; lv.y = l1;
        const size_t idx = (size_t)(n0 + n) * K + k0 + kp * 2;
        *(__nv_bfloat162*)(Whi + idx) = hv;
        *(__nv_bfloat162*)(Wlo + idx) = lv;
    }
}

// ============ fused work kernel: ROI align || trW1 || trW2 ============
__global__ __launch_bounds__(256)
void work_kernel(const float* __restrict__ featT,
                 const float* __restrict__ boxes,
                 const int*   __restrict__ rbatch,
                 __nv_bfloat16* __restrict__ fAh, __nv_bfloat16* __restrict__ fAl,
                 const float* __restrict__ fc1_w,
                 __nv_bfloat16* __restrict__ w1h, __nv_bfloat16* __restrict__ w1l,
                 const float* __restrict__ fc2_w,
                 __nv_bfloat16* __restrict__ w2h, __nv_bfloat16* __restrict__ w2l)
{
    __shared__ float tile[32][33];
    const int b = blockIdx.x;
    const int t = threadIdx.x;

    if (b < F_ROI_BLOCKS) {
        roi_align_dev(featT, boxes, rbatch, fAh, fAl, b, t);
    } else if (b < F_ROI_BLOCKS + F_W1_BLOCKS) {
        const int idx = b - F_ROI_BLOCKS;
        const int n0 = (idx & 31) * 32;
        const int k0 = (idx >> 5) * 32;
        transpose_dev<true>(tile, fc1_w, w1h, w1l, KDIM, HID, n0, k0, t);
    } else {
        const int idx = b - F_ROI_BLOCKS - F_W1_BLOCKS;
        const int n0 = (idx & 31) * 32;
        const int k0 = (idx >> 5) * 32;
        transpose_dev<false>(tile, fc2_w, w2h, w2l, HID, HID, n0, k0, t);
    }
}

// ================= split-bf16 mma.sync GEMM, split-K=3 =================
// 128x64 CTA tile, 128 thr, 3-stage, ONE sync/iter. Optional fused split-K
// combine in the epilogue via threadfence+ticket (last CTA per tile sums the
// 3 partials in fixed z-order, applies bias+relu, emits bf16 hi/lo).
#define BM 128
#define BN 64
#define BK 32
#define A_STAGE (BM * 64)                          // 8192 B
#define B_STAGE (BN * 64)                          // 4096 B
#define STAGE_BYTES (2 * A_STAGE + 2 * B_STAGE)    // 24576 B
#define GEMM_SMEM (3 * STAGE_BYTES)                // 73728 B

DEV void load_stage(uint32_t st,
                    const __nv_bfloat16* __restrict__ Ah,
                    const __nv_bfloat16* __restrict__ Al,
                    const __nv_bfloat16* __restrict__ Bh,
                    const __nv_bfloat16* __restrict__ Bl,
                    int M, int K, int m0, int n0, int k0, int tid)
{
    const uint32_t sAh = st;
    const uint32_t sAl = st + A_STAGE;
    const uint32_t sBh = st + 2 * A_STAGE;
    const uint32_t sBl = st + 2 * A_STAGE + B_STAGE;

    #pragma unroll
    for (int i = 0; i < 4; ++i) {
        const int q = tid + i * 128;
        const int row = q >> 2, cc = q & 3;
        const int gm = m0 + row;
        const int gmc = gm < M ? gm : (M - 1);
        const uint32_t ssize = gm < M ? 16u : 0u;
        const size_t goff = (size_t)gmc * K + k0 + cc * 8;
        const uint32_t so = swz((uint32_t)row, (uint32_t)cc);
        cp_async16(sAh + so, Ah + goff, ssize);
        cp_async16(sAl + so, Al + goff, ssize);
    }
    #pragma unroll
    for (int i = 0; i < 2; ++i) {
        const int q = tid + i * 128;
        const int row = q >> 2, cc = q & 3;
        const size_t goff = (size_t)(n0 + row) * K + k0 + cc * 8;
        const uint32_t so = swz((uint32_t)row, (uint32_t)cc);
        cp_async16(sBh + so, Bh + goff, 16u);
        cp_async16(sBl + so, Bl + goff, 16u);
    }
    cp_commit();
}

__global__ __launch_bounds__(128, 3)
void gemm_kernel(const __nv_bfloat16* __restrict__ Ah,
                 const __nv_bfloat16* __restrict__ Al,
                 const __nv_bfloat16* __restrict__ Bh,
                 const __nv_bfloat16* __restrict__ Bl,
                 float* __restrict__ part,
                 const float* __restrict__ bias,
                 __nv_bfloat16* __restrict__ outHi,
                 __nv_bfloat16* __restrict__ outLo,
                 int* __restrict__ ticket,
                 int M, int K)
{
    extern __shared__ __align__(128) char dsm[];
    const uint32_t base = smem_u32(dsm);

    const int tid = threadIdx.x;
    const int warp_m = tid >> 5;
    const int lane = tid & 31;
    const int m0 = blockIdx.x * BM;
    const int n0 = blockIdx.y * BN;

    const int Ttot = K / BK;
    const int z = blockIdx.z;
    const int t0 = (z * Ttot) / SPLITK;
    const int t1 = ((z + 1) * Ttot) / SPLITK;
    const int nT = t1 - t0;
    float* __restrict__ pz = part + (size_t)z * M * HID;

    float c[2][8][4];
    #pragma unroll
    for (int i = 0; i < 2; ++i)
        #pragma unroll
        for (int j = 0; j < 8; ++j)
            #pragma unroll
            for (int k = 0; k < 4; ++k) c[i][j][k] = 0.0f;

    load_stage(base,               Ah, Al, Bh, Bl, M, K, m0, n0, t0 * BK,       tid);
    load_stage(base + STAGE_BYTES, Ah, Al, Bh, Bl, M, K, m0, n0, (t0 + 1) * BK, tid);

    const int l8 = lane & 7;
    const uint32_t a_row0 = (uint32_t)(warp_m * 32 + l8 + ((lane >> 3) & 1) * 8);
    const uint32_t a_chunk0 = (uint32_t)(lane >> 4);      // + ks*2
    const uint32_t b_row0 = (uint32_t)l8;                  // + j*8
    const uint32_t b_chunk = (uint32_t)(lane >> 3);        // 0..3

    #pragma unroll 1
    for (int lt = 0; lt < nT; ++lt) {
        if (lt + 1 >= nT) cp_wait<0>(); else cp_wait<1>();
        __syncthreads();

        if (lt + 2 < nT)
            load_stage(base + ((lt + 2) % 3) * STAGE_BYTES, Ah, Al, Bh, Bl,
                       M, K, m0, n0, (t0 + lt + 2) * BK, tid);

        const uint32_t st = base + (lt % 3) * STAGE_BYTES;
        const uint32_t sAh = st;
        const uint32_t sAl = st + A_STAGE;
        const uint32_t sBh = st + 2 * A_STAGE;
        const uint32_t sBl = st + 2 * A_STAGE + B_STAGE;

        uint32_t ah[2][2][4], al[2][2][4];
        #pragma unroll
        for (int ma = 0; ma < 2; ++ma) {
            const uint32_t row = a_row0 + ma * 16;
            #pragma unroll
            for (int ks = 0; ks < 2; ++ks) {
                const uint32_t off = swz(row, a_chunk0 + ks * 2);
                ldm_x4(ah[ma][ks], sAh + off);
                ldm_x4(al[ma][ks], sAl + off);
            }
        }

        #pragma unroll
        for (int ch = 0; ch < 2; ++ch) {
            uint32_t bh[4][4], bl[4][4];
            #pragma unroll
            for (int j = 0; j < 4; ++j) {
                const uint32_t off = swz(b_row0 + (ch * 4 + j) * 8, b_chunk);
                ldm_x4(bh[j], sBh + off);
                ldm_x4(bl[j], sBl + off);
            }
            #pragma unroll
            for (int ks = 0; ks < 2; ++ks)
                #pragma unroll
                for (int ma = 0; ma < 2; ++ma)
                    #pragma unroll
                    for (int j = 0; j < 4; ++j) {
                        float* acc = c[ma][ch * 4 + j];
                        mma16816(acc, ah[ma][ks], bh[j] + ks * 2);
                        mma16816(acc, ah[ma][ks], bl[j] + ks * 2);
                        mma16816(acc, al[ma][ks], bh[j] + ks * 2);
                    }
        }
    }

    // ---- write fp32 partial ----
    const int row0 = lane >> 2;
    const int colp = (lane & 3) * 2;
    #pragma unroll
    for (int ma = 0; ma < 2; ++ma) {
        #pragma unroll
        for (int na = 0; na < 8; ++na) {
            const int n = n0 + na * 8 + colp;
            #pragma unroll
            for (int half = 0; half < 2; ++half) {
                const int m = m0 + warp_m * 32 + ma * 16 + row0 + half * 8;
                if (m < M)
                    *(float2*)(pz + (size_t)m * HID + n) =
                        make_float2(c[ma][na][half * 2 + 0], c[ma][na][half * 2 + 1]);
            }
        }
    }

    // ---- fused split-K combine (FC1 path): last CTA per tile finishes it ----
    if (outHi) {
        __threadfence();
        __shared__ int s_last;
        if (tid == 0) {
            const int old = atomicAdd(&ticket[blockIdx.x * 16 + blockIdx.y], 1);
            s_last = (old == SPLITK - 1) ? 1 : 0;
        }
        __syncthreads();
        if (s_last) {
            const size_t stride = (size_t)M * HID;
            // this 128x64 tile: 8192 elems = 4096 float2; 128 threads
            #pragma unroll 1
            for (int i = tid; i < BM * BN / 2; i += 128) {
                const int row = i >> 5;            // 0..127
                const int col = (i & 31) * 2;      // 0..62
                const int m = m0 + row;
                if (m >= M) continue;
                const size_t off = (size_t)m * HID + n0 + col;
                const float2 p0 = *(const float2*)(part + off);
                const float2 p1 = *(const float2*)(part + stride + off);
                const float2 p2 = *(const float2*)(part + 2 * stride + off);
                const float bv0 = bias[n0 + col], bv1 = bias[n0 + col + 1];
                const float v0 = fmaxf(p0.x + p1.x + p2.x + bv0, 0.0f);
                const float v1 = fmaxf(p0.y + p1.y + p2.y + bv1, 0.0f);
                __nv_bfloat16 h0, l0, h1, l1;
                split_bf16(v0, h0, l0);
                split_bf16(v1, h1, l1);
                __nv_bfloat162 hv; hv.x = h0; hv.y = h1;
                __nv_bfloat162 lv; lv.x = l0; lv.y = l1;
                *(__nv_bfloat162*)(outHi + off) = hv;
                *(__nv_bfloat162*)(outLo + off) = lv;
            }
        }
    }
}

// ===== fused heads: split-K combine + bias + relu + GEMV + softmax + decode
__global__ __launch_bounds__(256)
void head_kernel(const float* __restrict__ part,
                 const float* __restrict__ fc2_b,
                 const float* __restrict__ cls_w, const float* __restrict__ cls_b,
                 const float* __restrict__ bbox_w, const float* __restrict__ bbox_b,
                 const float* __restrict__ boxes,
                 float* __restrict__ out)
{
    const int r = blockIdx.x;
    const int t = threadIdx.x;
    float acc[10];
    #pragma unroll
    for (int j = 0; j < 10; ++j) acc[j] = 0.0f;

    const size_t stride = (size_t)NROI * HID;
    const float* p0 = part + (size_t)r * HID;
    #pragma unroll 1
    for (int k = t; k < HID; k += 256) {
        const float hv = fmaxf(p0[k] + p0[stride + k] + p0[2 * stride + k]
                               + fc2_b[k], 0.0f);
        acc[0] += hv * cls_w[k * 2 + 0];
        acc[1] += hv * cls_w[k * 2 + 1];
        #pragma unroll
        for (int j = 0; j < 8; ++j) acc[2 + j] += hv * bbox_w[k * 8 + j];
    }
    #pragma unroll
    for (int off = 16; off > 0; off >>= 1) {
        #pragma unroll
        for (int j = 0; j < 10; ++j)
            acc[j] += __shfl_down_sync(0xFFFFFFFFu, acc[j], off);
    }
    __shared__ float red[8][10];
    const int w = t >> 5, lane = t & 31;
    if (lane == 0) {
        #pragma unroll
        for (int j = 0; j < 10; ++j) red[w][j] = acc[j];
    }
    __syncthreads();
    if (t == 0) {
        float s[10];
        #pragma unroll
        for (int j = 0; j < 10; ++j) {
            float v = 0.0f;
            #pragma unroll
            for (int ww = 0; ww < 8; ++ww) v += red[ww][j];
            s[j] = v;
        }
        s[0] += cls_b[0]; s[1] += cls_b[1];
        #pragma unroll
        for (int j = 0; j < 8; ++j) s[2 + j] += bbox_b[j];

        const float mx = fmaxf(s[0], s[1]);
        const float e0 = expf(s[0] - mx), e1 = expf(s[1] - mx);
        const float inv = 1.0f / (e0 + e1);

        const float bx1 = boxes[r * 4 + 0], by1 = boxes[r * 4 + 1];
        const float bx2 = boxes[r * 4 + 2], by2 = boxes[r * 4 + 3];
        const float pw = bx2 - bx1, ph = by2 - by1;
        const float cx = bx1 + 0.5f * pw, cy = by1 + 0.5f * ph;
        #pragma unroll
        for (int k = 0; k < 2; ++k) {
            const float dx = s[2 + k * 4 + 0] * 0.1f;
            const float dy = s[2 + k * 4 + 1] * 0.1f;
            const float dw = fminf(s[2 + k * 4 + 2] * 0.2f, CLAMP_LOG);
            const float dh = fminf(s[2 + k * 4 + 3] * 0.2f, CLAMP_LOG);
            const float pcx = dx * pw + cx;
            const float pcy = dy * ph + cy;
            const float pww = expf(dw) * pw;
            const float phh = expf(dh) * ph;
            out[r * 10 + k * 4 + 0] = fminf(fmaxf(pcx - 0.5f * pww, 0.0f), IMG_W_);
            out[r * 10 + k * 4 + 1] = fminf(fmaxf(pcy - 0.5f * phh, 0.0f), IMG_H_);
            out[r * 10 + k * 4 + 2] = fminf(fmaxf(pcx + 0.5f * pww, 0.0f), IMG_W_);
            out[r * 10 + k * 4 + 3] = fminf(fmaxf(pcy + 0.5f * phh, 0.0f), IMG_H_);
        }
        out[r * 10 + 8] = e0 * inv;
        out[r * 10 + 9] = e1 * inv;
    }
}

// ================= launch =================
extern "C" void kernel_launch(void* const* d_in, const int* in_sizes, int n_in,
                              void* d_out, int out_size)
{
    const float* features = (const float*)d_in[0];
    const float* boxes    = (const float*)d_in[1];
    const int*   rbatch   = (const int*)  d_in[2];
    const float* fc1_w    = (const float*)d_in[3];
    const float* fc1_b    = (const float*)d_in[4];
    const float* fc2_w    = (const float*)d_in[5];
    const float* fc2_b    = (const float*)d_in[6];
    const float* cls_w    = (const float*)d_in[7];
    const float* cls_b    = (const float*)d_in[8];
    const float* bbox_w   = (const float*)d_in[9];
    const float* bbox_b   = (const float*)d_in[10];
    float* out = (float*)d_out;

    __nv_bfloat16 *fAh, *fAl, *w1h, *w1l, *w2h, *w2l, *h1h, *h1l;
    float *part_p, *featT_p;
    int* ticket_p;
    cudaGetSymbolAddress((void**)&featT_p, g_featT);
    cudaGetSymbolAddress((void**)&fAh, g_fA_hi);
    cudaGetSymbolAddress((void**)&fAl, g_fA_lo);
    cudaGetSymbolAddress((void**)&w1h, g_w1t_hi);
    cudaGetSymbolAddress((void**)&w1l, g_w1t_lo);
    cudaGetSymbolAddress((void**)&w2h, g_w2t_hi);
    cudaGetSymbolAddress((void**)&w2l, g_w2t_lo);
    cudaGetSymbolAddress((void**)&h1h, g_h1_hi);
    cudaGetSymbolAddress((void**)&h1l, g_h1_lo);
    cudaGetSymbolAddress((void**)&part_p, g_part);
    cudaGetSymbolAddress((void**)&ticket_p, g_ticket);

    cudaFuncSetAttribute(gemm_kernel, cudaFuncAttributeMaxDynamicSharedMemorySize,
                         GEMM_SMEM);

    // reset split-K tickets (graph-capturable memset node)
    cudaMemsetAsync(ticket_p, 0, 8 * 16 * sizeof(int));

    featT_kernel<<<dim3((FEAT_W + 31) / 32, FEAT_H, FEAT_B * 8), dim3(32, 8)>>>(
        features, featT_p);

    // fused: ROI align || W1 transpose (bin-major) || W2 transpose
    work_kernel<<<F_TOTAL, 256>>>(featT_p, boxes, rbatch, fAh, fAl,
                                  fc1_w, w1h, w1l, fc2_w, w2h, w2l);

    // FC1: split-K GEMM with fused combine (bias+relu -> h1 hi/lo)
    gemm_kernel<<<dim3(8, 16, SPLITK), 128, GEMM_SMEM>>>(
        fAh, fAl, w1h, w1l, part_p, fc1_b, h1h, h1l, ticket_p, NROI, KDIM);

    // FC2: partials only; head fuses the combine
    gemm_kernel<<<dim3(8, 16, SPLITK), 128, GEMM_SMEM>>>(
        h1h, h1l, w2h, w2l, part_p, nullptr, nullptr, nullptr, nullptr, NROI, HID);

    head_kernel<<<NROI, 256>>>(part_p, fc2_b, cls_w, cls_b, bbox_w, bbox_b, boxes, out);
    (void)in_sizes; (void)n_in; (void)out_size;
}

// round 15
// speedup vs baseline: 1.0480x; 1.0480x over previous
#include <cuda_runtime.h>
#include <cuda_bf16.h>
#include <stdint.h>

#define DEV __device__ __forceinline__

// ---------------- problem constants ----------------
#define FEAT_B 2
#define FEAT_C 256
#define FEAT_H 100
#define FEAT_W 136
#define NROI   1000
#define KDIM   12544      // 256*49; bin-major layout: k' = bin*256 + c
#define HID    1024
#define SPLITK 3
#define CLAMP_LOG 4.1351665567423560f   // ln(1000/16)
#define IMG_W_ 1088.0f
#define IMG_H_ 800.0f

// fused prep block ranges (featT || trW1 || trW2)
#define P_FEAT_BLOCKS ((FEAT_W + 31) / 32 * FEAT_H * FEAT_B * 8)     // 8000
#define P_W1_BLOCKS   ((HID / 32) * (KDIM / 32))                     // 12544
#define P_W2_BLOCKS   ((HID / 32) * (HID / 32))                      // 1024
#define P_TOTAL       (P_FEAT_BLOCKS + P_W1_BLOCKS + P_W2_BLOCKS)

// ---------------- scratch (device globals; no allocation allowed) --------
__device__ float         g_featT[FEAT_B * FEAT_H * FEAT_W * FEAT_C]; // channels-last
__device__ __nv_bfloat16 g_fA_hi[NROI * KDIM];
__device__ __nv_bfloat16 g_fA_lo[NROI * KDIM];
__device__ __nv_bfloat16 g_w1t_hi[HID * KDIM];
__device__ __nv_bfloat16 g_w1t_lo[HID * KDIM];
__device__ __nv_bfloat16 g_w2t_hi[HID * HID];
__device__ __nv_bfloat16 g_w2t_lo[HID * HID];
__device__ __nv_bfloat16 g_h1_hi[NROI * HID];
__device__ __nv_bfloat16 g_h1_lo[NROI * HID];
__device__ float         g_part[SPLITK * NROI * HID];   // split-K partials

// ---------------- helpers ----------------
DEV uint32_t smem_u32(const void* p) {
    uint32_t a;
    asm("{ .reg .u64 t; cvta.to.shared.u64 t, %1; cvt.u32.u64 %0, t; }" : "=r"(a) : "l"(p));
    return a;
}
DEV void cp_async16(uint32_t dst, const void* src, uint32_t src_size) {
    asm volatile("cp.async.cg.shared.global [%0], [%1], 16, %2;"
                 :: "r"(dst), "l"(src), "r"(src_size) : "memory");
}
DEV void cp_commit() { asm volatile("cp.async.commit_group;" ::: "memory"); }
template <int N>
DEV void cp_wait() { asm volatile("cp.async.wait_group %0;" :: "n"(N) : "memory"); }

DEV void ldm_x4(uint32_t* r, uint32_t addr) {
    asm volatile("ldmatrix.sync.aligned.m8n8.x4.shared.b16 {%0,%1,%2,%3}, [%4];"
                 : "=r"(r[0]), "=r"(r[1]), "=r"(r[2]), "=r"(r[3]) : "r"(addr));
}
DEV void mma16816(float* c, const uint32_t* a, const uint32_t* b) {
    asm volatile(
        "mma.sync.aligned.m16n8k16.row.col.f32.bf16.bf16.f32 "
        "{%0,%1,%2,%3}, {%4,%5,%6,%7}, {%8,%9}, {%0,%1,%2,%3};"
        : "+f"(c[0]), "+f"(c[1]), "+f"(c[2]), "+f"(c[3])
        : "r"(a[0]), "r"(a[1]), "r"(a[2]), "r"(a[3]), "r"(b[0]), "r"(b[1]));
}
DEV void split_bf16(float v, __nv_bfloat16& hi, __nv_bfloat16& lo) {
    hi = __float2bfloat16(v);
    lo = __float2bfloat16(v - __bfloat162float(hi));
}
// 64B-row XOR swizzle: 16B chunk index c in row r -> c ^ ((r>>1)&3)
DEV uint32_t swz(uint32_t row, uint32_t chunk) {
    return row * 64u + ((chunk ^ ((row >> 1) & 3u)) << 4);
}

// ================= fused prep: featT || trW1(bin-major) || trW2 =========
DEV void featT_dev(float tile[32][33],
                   const float* __restrict__ feat, float* __restrict__ featT,
                   int bz, int h, int w0, int t)
{
    const int b  = bz >> 3;
    const int cb = bz & 7;
    const int tx = t & 31, ty = t >> 5;

    const float* src = feat + ((size_t)b * FEAT_C + cb * 32) * (FEAT_H * FEAT_W)
                            + (size_t)h * FEAT_W;
    #pragma unroll
    for (int i = 0; i < 4; ++i) {
        const int w = w0 + tx;
        if (w < FEAT_W)
            tile[ty + i * 8][tx] = src[(size_t)(ty + i * 8) * (FEAT_H * FEAT_W) + w];
    }
    __syncthreads();
    float* dst = featT + ((size_t)(b * FEAT_H + h) * FEAT_W) * FEAT_C + cb * 32;
    #pragma unroll
    for (int i = 0; i < 4; ++i) {
        const int w = w0 + ty + i * 8;
        if (w < FEAT_W)
            dst[(size_t)w * FEAT_C + tx] = tile[tx][ty + i * 8];
    }
}

// transpose Wsrc[K][N] -> Wdst[N][K'] bf16 hi/lo. REORDER => bin-major perm.
template <bool REORDER>
DEV void transpose_dev(float tile[32][33],
                       const float* __restrict__ Wsrc,
                       __nv_bfloat16* __restrict__ Whi,
                       __nv_bfloat16* __restrict__ Wlo,
                       int K, int N, int n0, int k0, int t)
{
    const int tx = t & 31, ty = t >> 5;
    #pragma unroll
    for (int i = 0; i < 4; ++i) {
        const int kp = k0 + ty + i * 8;
        const int ksrc = REORDER ? ((kp & 255) * 49 + (kp >> 8)) : kp;
        tile[ty + i * 8][tx] = Wsrc[(size_t)ksrc * N + n0 + tx];
    }
    __syncthreads();
    #pragma unroll
    for (int it = 0; it < 2; ++it) {
        const int item = t + it * 256;        // 0..511 over (n, kpair)
        const int n = item >> 4;
        const int kp = item & 15;
        const float v0 = tile[kp * 2][n];
        const float v1 = tile[kp * 2 + 1][n];
        __nv_bfloat16 h0, l0, h1, l1;
        split_bf16(v0, h0, l0);
        split_bf16(v1, h1, l1);
        __nv_bfloat162 hv; hv.x = h0; hv.y = h1;
        __nv_bfloat162 lv; lv.x = l0; lv.y = l1;
        const size_t idx = (size_t)(n0 + n) * K + k0 + kp * 2;
        *(__nv_bfloat162*)(Whi + idx) = hv;
        *(__nv_bfloat162*)(Wlo + idx) = lv;
    }
}

__global__ __launch_bounds__(256)
void prep_kernel(const float* __restrict__ feat, float* __restrict__ featT,
                 const float* __restrict__ fc1_w,
                 __nv_bfloat16* __restrict__ w1h, __nv_bfloat16* __restrict__ w1l,
                 const float* __restrict__ fc2_w,
                 __nv_bfloat16* __restrict__ w2h, __nv_bfloat16* __restrict__ w2l)
{
    __shared__ float tile[32][33];
    const int b = blockIdx.x;
    const int t = threadIdx.x;
    const int WX = (FEAT_W + 31) / 32;     // 5

    if (b < P_FEAT_BLOCKS) {
        const int wx = b % WX;
        const int h  = (b / WX) % FEAT_H;
        const int bz = b / (WX * FEAT_H);
        featT_dev(tile, feat, featT, bz, h, wx * 32, t);
    } else if (b < P_FEAT_BLOCKS + P_W1_BLOCKS) {
        const int idx = b - P_FEAT_BLOCKS;
        const int n0 = (idx & 31) * 32;
        const int k0 = (idx >> 5) * 32;
        transpose_dev<true>(tile, fc1_w, w1h, w1l, KDIM, HID, n0, k0, t);
    } else {
        const int idx = b - P_FEAT_BLOCKS - P_W1_BLOCKS;
        const int n0 = (idx & 31) * 32;
        const int k0 = (idx >> 5) * 32;
        transpose_dev<false>(tile, fc2_w, w2h, w2l, HID, HID, n0, k0, t);
    }
}

// ================= ROI align v4: bin-major output, direct stores =========
__global__ __launch_bounds__(256)
void roi_align4_kernel(const float* __restrict__ featT,
                       const float* __restrict__ boxes,
                       const int*   __restrict__ rbatch,
                       __nv_bfloat16* __restrict__ out_hi,
                       __nv_bfloat16* __restrict__ out_lo)
{
    const int r = blockIdx.x;
    const int t = threadIdx.x;
    const int half = t >> 7;
    const int c0 = (t & 127) * 2;

    __shared__ float sly[14], slx[14];
    __shared__ int   siy0[14], siy1[14], six0c[14], six1c[14];
    __shared__ float box4[4];
    __shared__ int   sb;

    if (t < 4) box4[t] = boxes[r * 4 + t];
    if (t == 4) sb = rbatch[r];
    __syncthreads();

    const float x1 = box4[0] * 0.125f, y1v = box4[1] * 0.125f;
    const float x2 = box4[2] * 0.125f, y2v = box4[3] * 0.125f;
    const float rw = fmaxf(x2 - x1, 1.0f);
    const float rh = fmaxf(y2v - y1v, 1.0f);
    const float bw = rw * (1.0f / 7.0f);
    const float bh = rh * (1.0f / 7.0f);

    if (t < 28) {
        const int p = t % 14;
        const float off = (float)(p >> 1) + ((float)(p & 1) + 0.5f) * 0.5f;
        if (t < 14) {
            float y = y1v + off * bh;
            y = fminf(fmaxf(y, 0.0f), (float)(FEAT_H - 1));
            float y0 = floorf(y);
            int y0i = (int)y0;
            siy0[p] = y0i;
            siy1[p] = min(y0i + 1, FEAT_H - 1);
            sly[p] = y - y0;
        } else {
            float x = x1 + off * bw;
            x = fminf(fmaxf(x, 0.0f), (float)(FEAT_W - 1));
            float x0 = floorf(x);
            int x0i = (int)x0;
            six0c[p] = x0i * FEAT_C;
            six1c[p] = min(x0i + 1, FEAT_W - 1) * FEAT_C;
            slx[p] = x - x0;
        }
    }
    __syncthreads();

    const float* fb = featT + (size_t)sb * (FEAT_H * FEAT_W * FEAT_C) + c0;
    __nv_bfloat16* gh = out_hi + (size_t)r * KDIM + c0;
    __nv_bfloat16* gl = out_lo + (size_t)r * KDIM + c0;

    const int byBeg = half ? 4 : 0;
    const int byEnd = half ? 7 : 4;

    #pragma unroll 1
    for (int by = byBeg; by < byEnd; ++by) {
        float accx[7], accy[7];
        #pragma unroll
        for (int j = 0; j < 7; ++j) { accx[j] = 0.0f; accy[j] = 0.0f; }

        #pragma unroll
        for (int sy = 0; sy < 2; ++sy) {
            const int py = by * 2 + sy;
            const float ly = sly[py];
            const float* r0 = fb + (size_t)(siy0[py] * FEAT_W) * FEAT_C;
            const float* r1 = fb + (size_t)(siy1[py] * FEAT_W) * FEAT_C;
            #pragma unroll
            for (int px = 0; px < 14; ++px) {
                const int x0c = six0c[px], x1c = six1c[px];
                const float lx = slx[px];
                const float2 v00 = *(const float2*)(r0 + x0c);
                const float2 v01 = *(const float2*)(r0 + x1c);
                const float2 v10 = *(const float2*)(r1 + x0c);
                const float2 v11 = *(const float2*)(r1 + x1c);
                const float topx = v00.x + (v01.x - v00.x) * lx;
                const float botx = v10.x + (v11.x - v10.x) * lx;
                const float topy = v00.y + (v01.y - v00.y) * lx;
                const float boty = v10.y + (v11.y - v10.y) * lx;
                accx[px >> 1] += topx + (botx - topx) * ly;
                accy[px >> 1] += topy + (boty - topy) * ly;
            }
        }
        #pragma unroll
        for (int bx = 0; bx < 7; ++bx) {
            const int bin = by * 7 + bx;
            __nv_bfloat16 hx, lxo, hy, lyo;
            split_bf16(accx[bx] * 0.25f, hx, lxo);
            split_bf16(accy[bx] * 0.25f, hy, lyo);
            __nv_bfloat162 hv; hv.x = hx; hv.y = hy;
            __nv_bfloat162 lv; lv.x = lxo; lv.y = lyo;
            *(__nv_bfloat162*)(gh + bin * 256) = hv;
            *(__nv_bfloat162*)(gl + bin * 256) = lv;
        }
    }
}

// ================= split-bf16 mma.sync GEMM, split-K=3 (R10 proven) =====
#define BM 128
#define BN 64
#define BK 32
#define A_STAGE (BM * 64)                          // 8192 B
#define B_STAGE (BN * 64)                          // 4096 B
#define STAGE_BYTES (2 * A_STAGE + 2 * B_STAGE)    // 24576 B
#define GEMM_SMEM (3 * STAGE_BYTES)                // 73728 B

DEV void load_stage(uint32_t st,
                    const __nv_bfloat16* __restrict__ Ah,
                    const __nv_bfloat16* __restrict__ Al,
                    const __nv_bfloat16* __restrict__ Bh,
                    const __nv_bfloat16* __restrict__ Bl,
                    int M, int K, int m0, int n0, int k0, int tid)
{
    const uint32_t sAh = st;
    const uint32_t sAl = st + A_STAGE;
    const uint32_t sBh = st + 2 * A_STAGE;
    const uint32_t sBl = st + 2 * A_STAGE + B_STAGE;

    #pragma unroll
    for (int i = 0; i < 4; ++i) {
        const int q = tid + i * 128;
        const int row = q >> 2, cc = q & 3;
        const int gm = m0 + row;
        const int gmc = gm < M ? gm : (M - 1);
        const uint32_t ssize = gm < M ? 16u : 0u;
        const size_t goff = (size_t)gmc * K + k0 + cc * 8;
        const uint32_t so = swz((uint32_t)row, (uint32_t)cc);
        cp_async16(sAh + so, Ah + goff, ssize);
        cp_async16(sAl + so, Al + goff, ssize);
    }
    #pragma unroll
    for (int i = 0; i < 2; ++i) {
        const int q = tid + i * 128;
        const int row = q >> 2, cc = q & 3;
        const size_t goff = (size_t)(n0 + row) * K + k0 + cc * 8;
        const uint32_t so = swz((uint32_t)row, (uint32_t)cc);
        cp_async16(sBh + so, Bh + goff, 16u);
        cp_async16(sBl + so, Bl + goff, 16u);
    }
    cp_commit();
}

__global__ __launch_bounds__(128, 3)
void gemm_kernel(const __nv_bfloat16* __restrict__ Ah,
                 const __nv_bfloat16* __restrict__ Al,
                 const __nv_bfloat16* __restrict__ Bh,
                 const __nv_bfloat16* __restrict__ Bl,
                 float* __restrict__ part,
                 int M, int K)
{
    extern __shared__ __align__(128) char dsm[];
    const uint32_t base = smem_u32(dsm);

    const int tid = threadIdx.x;
    const int warp_m = tid >> 5;
    const int lane = tid & 31;
    const int m0 = blockIdx.x * BM;
    const int n0 = blockIdx.y * BN;

    const int Ttot = K / BK;
    const int z = blockIdx.z;
    const int t0 = (z * Ttot) / SPLITK;
    const int t1 = ((z + 1) * Ttot) / SPLITK;
    const int nT = t1 - t0;
    float* __restrict__ pz = part + (size_t)z * M * HID;

    float c[2][8][4];
    #pragma unroll
    for (int i = 0; i < 2; ++i)
        #pragma unroll
        for (int j = 0; j < 8; ++j)
            #pragma unroll
            for (int k = 0; k < 4; ++k) c[i][j][k] = 0.0f;

    load_stage(base,               Ah, Al, Bh, Bl, M, K, m0, n0, t0 * BK,       tid);
    load_stage(base + STAGE_BYTES, Ah, Al, Bh, Bl, M, K, m0, n0, (t0 + 1) * BK, tid);

    const int l8 = lane & 7;
    const uint32_t a_row0 = (uint32_t)(warp_m * 32 + l8 + ((lane >> 3) & 1) * 8);
    const uint32_t a_chunk0 = (uint32_t)(lane >> 4);      // + ks*2
    const uint32_t b_row0 = (uint32_t)l8;                  // + j*8
    const uint32_t b_chunk = (uint32_t)(lane >> 3);        // 0..3

    #pragma unroll 1
    for (int lt = 0; lt < nT; ++lt) {
        if (lt + 1 >= nT) cp_wait<0>(); else cp_wait<1>();
        __syncthreads();

        if (lt + 2 < nT)
            load_stage(base + ((lt + 2) % 3) * STAGE_BYTES, Ah, Al, Bh, Bl,
                       M, K, m0, n0, (t0 + lt + 2) * BK, tid);

        const uint32_t st = base + (lt % 3) * STAGE_BYTES;
        const uint32_t sAh = st;
        const uint32_t sAl = st + A_STAGE;
        const uint32_t sBh = st + 2 * A_STAGE;
        const uint32_t sBl = st + 2 * A_STAGE + B_STAGE;

        uint32_t ah[2][2][4], al[2][2][4];
        #pragma unroll
        for (int ma = 0; ma < 2; ++ma) {
            const uint32_t row = a_row0 + ma * 16;
            #pragma unroll
            for (int ks = 0; ks < 2; ++ks) {
                const uint32_t off = swz(row, a_chunk0 + ks * 2);
                ldm_x4(ah[ma][ks], sAh + off);
                ldm_x4(al[ma][ks], sAl + off);
            }
        }

        #pragma unroll
        for (int ch = 0; ch < 2; ++ch) {
            uint32_t bh[4][4], bl[4][4];
            #pragma unroll
            for (int j = 0; j < 4; ++j) {
                const uint32_t off = swz(b_row0 + (ch * 4 + j) * 8, b_chunk);
                ldm_x4(bh[j], sBh + off);
                ldm_x4(bl[j], sBl + off);
            }
            #pragma unroll
            for (int ks = 0; ks < 2; ++ks)
                #pragma unroll
                for (int ma = 0; ma < 2; ++ma)
                    #pragma unroll
                    for (int j = 0; j < 4; ++j) {
                        float* acc = c[ma][ch * 4 + j];
                        mma16816(acc, ah[ma][ks], bh[j] + ks * 2);
                        mma16816(acc, ah[ma][ks], bl[j] + ks * 2);
                        mma16816(acc, al[ma][ks], bh[j] + ks * 2);
                    }
        }
    }

    const int row0 = lane >> 2;
    const int colp = (lane & 3) * 2;
    #pragma unroll
    for (int ma = 0; ma < 2; ++ma) {
        #pragma unroll
        for (int na = 0; na < 8; ++na) {
            const int n = n0 + na * 8 + colp;
            #pragma unroll
            for (int half = 0; half < 2; ++half) {
                const int m = m0 + warp_m * 32 + ma * 16 + row0 + half * 8;
                if (m < M)
                    *(float2*)(pz + (size_t)m * HID + n) =
                        make_float2(c[ma][na][half * 2 + 0], c[ma][na][half * 2 + 1]);
            }
        }
    }
}

// ========== split-K combine + bias + relu (FC1), float4 vectorized ======
__global__ __launch_bounds__(256)
void combine_kernel(const float* __restrict__ part,
                    const float* __restrict__ bias,
                    __nv_bfloat16* __restrict__ outHi,
                    __nv_bfloat16* __restrict__ outLo,
                    int M)
{
    const int idx = blockIdx.x * 256 + threadIdx.x;       // one float4 each
    if (idx * 4 >= M * HID) return;
    const size_t stride = (size_t)M * HID;
    const float4 p0 = *(const float4*)(part + idx * 4);
    const float4 p1 = *(const float4*)(part + stride + idx * 4);
    const float4 p2 = *(const float4*)(part + 2 * stride + idx * 4);
    const int n = (idx * 4) & (HID - 1);
    const float4 bv = *(const float4*)(bias + n);
    const float v0 = fmaxf(p0.x + p1.x + p2.x + bv.x, 0.0f);
    const float v1 = fmaxf(p0.y + p1.y + p2.y + bv.y, 0.0f);
    const float v2 = fmaxf(p0.z + p1.z + p2.z + bv.z, 0.0f);
    const float v3 = fmaxf(p0.w + p1.w + p2.w + bv.w, 0.0f);
    __nv_bfloat16 h0, l0, h1, l1, h2, l2, h3, l3;
    split_bf16(v0, h0, l0); split_bf16(v1, h1, l1);
    split_bf16(v2, h2, l2); split_bf16(v3, h3, l3);
    __nv_bfloat162 hv01; hv01.x = h0; hv01.y = h1;
    __nv_bfloat162 hv23; hv23.x = h2; hv23.y = h3;
    __nv_bfloat162 lv01; lv01.x = l0; lv01.y = l1;
    __nv_bfloat162 lv23; lv23.x = l2; lv23.y = l3;
    *(__nv_bfloat162*)(outHi + idx * 4)     = hv01;
    *(__nv_bfloat162*)(outHi + idx * 4 + 2) = hv23;
    *(__nv_bfloat162*)(outLo + idx * 4)     = lv01;
    *(__nv_bfloat162*)(outLo + idx * 4 + 2) = lv23;
}

// ===== fused heads: combine + bias + relu + GEMV + softmax + decode =====
// 256 threads; thread t owns k in [t*4, t*4+4) (single pass, all float4).
__global__ __launch_bounds__(256)
void head_kernel(const float* __restrict__ part,
                 const float* __restrict__ fc2_b,
                 const float* __restrict__ cls_w, const float* __restrict__ cls_b,
                 const float* __restrict__ bbox_w, const float* __restrict__ bbox_b,
                 const float* __restrict__ boxes,
                 float* __restrict__ out)
{
    const int r = blockIdx.x;
    const int t = threadIdx.x;
    const int k = t * 4;

    const size_t stride = (size_t)NROI * HID;
    const float* p0 = part + (size_t)r * HID;

    const float4 a0 = *(const float4*)(p0 + k);
    const float4 a1 = *(const float4*)(p0 + stride + k);
    const float4 a2 = *(const float4*)(p0 + 2 * stride + k);
    const float4 bb = *(const float4*)(fc2_b + k);
    float hv[4];
    hv[0] = fmaxf(a0.x + a1.x + a2.x + bb.x, 0.0f);
    hv[1] = fmaxf(a0.y + a1.y + a2.y + bb.y, 0.0f);
    hv[2] = fmaxf(a0.z + a1.z + a2.z + bb.z, 0.0f);
    hv[3] = fmaxf(a0.w + a1.w + a2.w + bb.w, 0.0f);

    float acc[10];
    #pragma unroll
    for (int j = 0; j < 10; ++j) acc[j] = 0.0f;

    // cls_w rows k..k+3, 2 cols each: 8 floats contiguous
    {
        const float4 c01 = *(const float4*)(cls_w + k * 2);
        const float4 c23 = *(const float4*)(cls_w + k * 2 + 4);
        acc[0] = hv[0] * c01.x + hv[1] * c01.z + hv[2] * c23.x + hv[3] * c23.z;
        acc[1] = hv[0] * c01.y + hv[1] * c01.w + hv[2] * c23.y + hv[3] * c23.w;
    }
    // bbox_w rows k..k+3, 8 cols each: 32 floats contiguous
    #pragma unroll
    for (int kk = 0; kk < 4; ++kk) {
        const float4 b0 = *(const float4*)(bbox_w + (k + kk) * 8);
        const float4 b1 = *(const float4*)(bbox_w + (k + kk) * 8 + 4);
        acc[2] += hv[kk] * b0.x; acc[3] += hv[kk] * b0.y;
        acc[4] += hv[kk] * b0.z; acc[5] += hv[kk] * b0.w;
        acc[6] += hv[kk] * b1.x; acc[7] += hv[kk] * b1.y;
        acc[8] += hv[kk] * b1.z; acc[9] += hv[kk] * b1.w;
    }

    #pragma unroll
    for (int off = 16; off > 0; off >>= 1) {
        #pragma unroll
        for (int j = 0; j < 10; ++j)
            acc[j] += __shfl_down_sync(0xFFFFFFFFu, acc[j], off);
    }
    __shared__ float red[8][10];
    const int w = t >> 5, lane = t & 31;
    if (lane == 0) {
        #pragma unroll
        for (int j = 0; j < 10; ++j) red[w][j] = acc[j];
    }
    __syncthreads();
    if (t == 0) {
        float s[10];
        #pragma unroll
        for (int j = 0; j < 10; ++j) {
            float v = 0.0f;
            #pragma unroll
            for (int ww = 0; ww < 8; ++ww) v += red[ww][j];
            s[j] = v;
        }
        s[0] += cls_b[0]; s[1] += cls_b[1];
        #pragma unroll
        for (int j = 0; j < 8; ++j) s[2 + j] += bbox_b[j];

        const float mx = fmaxf(s[0], s[1]);
        const float e0 = expf(s[0] - mx), e1 = expf(s[1] - mx);
        const float inv = 1.0f / (e0 + e1);

        const float bx1 = boxes[r * 4 + 0], by1 = boxes[r * 4 + 1];
        const float bx2 = boxes[r * 4 + 2], by2 = boxes[r * 4 + 3];
        const float pw = bx2 - bx1, ph = by2 - by1;
        const float cx = bx1 + 0.5f * pw, cy = by1 + 0.5f * ph;
        #pragma unroll
        for (int kcl = 0; kcl < 2; ++kcl) {
            const float dx = s[2 + kcl * 4 + 0] * 0.1f;
            const float dy = s[2 + kcl * 4 + 1] * 0.1f;
            const float dw = fminf(s[2 + kcl * 4 + 2] * 0.2f, CLAMP_LOG);
            const float dh = fminf(s[2 + kcl * 4 + 3] * 0.2f, CLAMP_LOG);
            const float pcx = dx * pw + cx;
            const float pcy = dy * ph + cy;
            const float pww = expf(dw) * pw;
            const float phh = expf(dh) * ph;
            out[r * 10 + kcl * 4 + 0] = fminf(fmaxf(pcx - 0.5f * pww, 0.0f), IMG_W_);
            out[r * 10 + kcl * 4 + 1] = fminf(fmaxf(pcy - 0.5f * phh, 0.0f), IMG_H_);
            out[r * 10 + kcl * 4 + 2] = fminf(fmaxf(pcx + 0.5f * pww, 0.0f), IMG_W_);
            out[r * 10 + kcl * 4 + 3] = fminf(fmaxf(pcy + 0.5f * phh, 0.0f), IMG_H_);
        }
        out[r * 10 + 8] = e0 * inv;
        out[r * 10 + 9] = e1 * inv;
    }
}

// ================= launch =================
extern "C" void kernel_launch(void* const* d_in, const int* in_sizes, int n_in,
                              void* d_out, int out_size)
{
    const float* features = (const float*)d_in[0];
    const float* boxes    = (const float*)d_in[1];
    const int*   rbatch   = (const int*)  d_in[2];
    const float* fc1_w    = (const float*)d_in[3];
    const float* fc1_b    = (const float*)d_in[4];
    const float* fc2_w    = (const float*)d_in[5];
    const float* fc2_b    = (const float*)d_in[6];
    const float* cls_w    = (const float*)d_in[7];
    const float* cls_b    = (const float*)d_in[8];
    const float* bbox_w   = (const float*)d_in[9];
    const float* bbox_b   = (const float*)d_in[10];
    float* out = (float*)d_out;

    __nv_bfloat16 *fAh, *fAl, *w1h, *w1l, *w2h, *w2l, *h1h, *h1l;
    float *part_p, *featT_p;
    cudaGetSymbolAddress((void**)&featT_p, g_featT);
    cudaGetSymbolAddress((void**)&fAh, g_fA_hi);
    cudaGetSymbolAddress((void**)&fAl, g_fA_lo);
    cudaGetSymbolAddress((void**)&w1h, g_w1t_hi);
    cudaGetSymbolAddress((void**)&w1l, g_w1t_lo);
    cudaGetSymbolAddress((void**)&w2h, g_w2t_hi);
    cudaGetSymbolAddress((void**)&w2l, g_w2t_lo);
    cudaGetSymbolAddress((void**)&h1h, g_h1_hi);
    cudaGetSymbolAddress((void**)&h1l, g_h1_lo);
    cudaGetSymbolAddress((void**)&part_p, g_part);

    cudaFuncSetAttribute(gemm_kernel, cudaFuncAttributeMaxDynamicSharedMemorySize,
                         GEMM_SMEM);

    const int combine_blocks = (NROI * HID / 4 + 255) / 256;

    // fused prep: featT || W1 transpose (bin-major) || W2 transpose
    prep_kernel<<<P_TOTAL, 256>>>(features, featT_p,
                                  fc1_w, w1h, w1l, fc2_w, w2h, w2l);
    roi_align4_kernel<<<NROI, 256>>>(featT_p, boxes, rbatch, fAh, fAl);

    gemm_kernel<<<dim3(8, 16, SPLITK), 128, GEMM_SMEM>>>(fAh, fAl, w1h, w1l, part_p,
                                                         NROI, KDIM);
    combine_kernel<<<combine_blocks, 256>>>(part_p, fc1_b, h1h, h1l, NROI);

    gemm_kernel<<<dim3(8, 16, SPLITK), 128, GEMM_SMEM>>>(h1h, h1l, w2h, w2l, part_p,
                                                         NROI, HID);

    head_kernel<<<NROI, 256>>>(part_p, fc2_b, cls_w, cls_b, bbox_w, bbox_b, boxes, out);
    (void)in_sizes; (void)n_in; (void)out_size;
}

// round 16
// speedup vs baseline: 1.0612x; 1.0126x over previous
#include <cuda_runtime.h>
#include <cuda_bf16.h>
#include <stdint.h>

#define DEV __device__ __forceinline__

// ---------------- problem constants ----------------
#define FEAT_B 2
#define FEAT_C 256
#define FEAT_H 100
#define FEAT_W 136
#define NROI   1000
#define KDIM   12544      // 256*49; bin-major layout: k' = bin*256 + c
#define HID    1024
#define SPLITK 3
#define CLAMP_LOG 4.1351665567423560f   // ln(1000/16)
#define IMG_W_ 1088.0f
#define IMG_H_ 800.0f

// fused prep block ranges (featT || trW1 || trW2)
#define P_FEAT_BLOCKS ((FEAT_W + 31) / 32 * FEAT_H * FEAT_B * 8)     // 8000
#define P_W1_BLOCKS   ((HID / 32) * (KDIM / 32))                     // 12544
#define P_W2_BLOCKS   ((HID / 32) * (HID / 32))                      // 1024
#define P_TOTAL       (P_FEAT_BLOCKS + P_W1_BLOCKS + P_W2_BLOCKS)

// ---------------- scratch (device globals; no allocation allowed) --------
__device__ float         g_featT[FEAT_B * FEAT_H * FEAT_W * FEAT_C]; // channels-last
__device__ __nv_bfloat16 g_fA_hi[NROI * KDIM];
__device__ __nv_bfloat16 g_fA_lo[NROI * KDIM];
__device__ __nv_bfloat16 g_w1t_hi[HID * KDIM];
__device__ __nv_bfloat16 g_w1t_lo[HID * KDIM];
__device__ __nv_bfloat16 g_w2t_hi[HID * HID];
__device__ __nv_bfloat16 g_w2t_lo[HID * HID];
__device__ __nv_bfloat16 g_h1_hi[NROI * HID];
__device__ __nv_bfloat16 g_h1_lo[NROI * HID];
__device__ float         g_part[SPLITK * NROI * HID];   // split-K partials

// ---------------- helpers ----------------
DEV uint32_t smem_u32(const void* p) {
    uint32_t a;
    asm("{ .reg .u64 t; cvta.to.shared.u64 t, %1; cvt.u32.u64 %0, t; }" : "=r"(a) : "l"(p));
    return a;
}
DEV void cp_async16(uint32_t dst, const void* src, uint32_t src_size) {
    asm volatile("cp.async.cg.shared.global [%0], [%1], 16, %2;"
                 :: "r"(dst), "l"(src), "r"(src_size) : "memory");
}
DEV void cp_commit() { asm volatile("cp.async.commit_group;" ::: "memory"); }
template <int N>
DEV void cp_wait() { asm volatile("cp.async.wait_group %0;" :: "n"(N) : "memory"); }

DEV void ldm_x4(uint32_t* r, uint32_t addr) {
    asm volatile("ldmatrix.sync.aligned.m8n8.x4.shared.b16 {%0,%1,%2,%3}, [%4];"
                 : "=r"(r[0]), "=r"(r[1]), "=r"(r[2]), "=r"(r[3]) : "r"(addr));
}
DEV void mma16816(float* c, const uint32_t* a, const uint32_t* b) {
    asm volatile(
        "mma.sync.aligned.m16n8k16.row.col.f32.bf16.bf16.f32 "
        "{%0,%1,%2,%3}, {%4,%5,%6,%7}, {%8,%9}, {%0,%1,%2,%3};"
        : "+f"(c[0]), "+f"(c[1]), "+f"(c[2]), "+f"(c[3])
        : "r"(a[0]), "r"(a[1]), "r"(a[2]), "r"(a[3]), "r"(b[0]), "r"(b[1]));
}
DEV void split_bf16(float v, __nv_bfloat16& hi, __nv_bfloat16& lo) {
    hi = __float2bfloat16(v);
    lo = __float2bfloat16(v - __bfloat162float(hi));
}
// 64B-row XOR swizzle: 16B chunk index c in row r -> c ^ ((r>>1)&3)
DEV uint32_t swz(uint32_t row, uint32_t chunk) {
    return row * 64u + ((chunk ^ ((row >> 1) & 3u)) << 4);
}

// ================= fused prep: featT || trW1(bin-major) || trW2 =========
DEV void featT_dev(float tile[32][33],
                   const float* __restrict__ feat, float* __restrict__ featT,
                   int bz, int h, int w0, int t)
{
    const int b  = bz >> 3;
    const int cb = bz & 7;
    const int tx = t & 31, ty = t >> 5;

    const float* src = feat + ((size_t)b * FEAT_C + cb * 32) * (FEAT_H * FEAT_W)
                            + (size_t)h * FEAT_W;
    #pragma unroll
    for (int i = 0; i < 4; ++i) {
        const int w = w0 + tx;
        if (w < FEAT_W)
            tile[ty + i * 8][tx] = src[(size_t)(ty + i * 8) * (FEAT_H * FEAT_W) + w];
    }
    __syncthreads();
    float* dst = featT + ((size_t)(b * FEAT_H + h) * FEAT_W) * FEAT_C + cb * 32;
    #pragma unroll
    for (int i = 0; i < 4; ++i) {
        const int w = w0 + ty + i * 8;
        if (w < FEAT_W)
            dst[(size_t)w * FEAT_C + tx] = tile[tx][ty + i * 8];
    }
}

// transpose Wsrc[K][N] -> Wdst[N][K'] bf16 hi/lo. REORDER => bin-major perm.
template <bool REORDER>
DEV void transpose_dev(float tile[32][33],
                       const float* __restrict__ Wsrc,
                       __nv_bfloat16* __restrict__ Whi,
                       __nv_bfloat16* __restrict__ Wlo,
                       int K, int N, int n0, int k0, int t)
{
    const int tx = t & 31, ty = t >> 5;
    #pragma unroll
    for (int i = 0; i < 4; ++i) {
        const int kp = k0 + ty + i * 8;
        const int ksrc = REORDER ? ((kp & 255) * 49 + (kp >> 8)) : kp;
        tile[ty + i * 8][tx] = Wsrc[(size_t)ksrc * N + n0 + tx];
    }
    __syncthreads();
    #pragma unroll
    for (int it = 0; it < 2; ++it) {
        const int item = t + it * 256;        // 0..511 over (n, kpair)
        const int n = item >> 4;
        const int kp = item & 15;
        const float v0 = tile[kp * 2][n];
        const float v1 = tile[kp * 2 + 1][n];
        __nv_bfloat16 h0, l0, h1, l1;
        split_bf16(v0, h0, l0);
        split_bf16(v1, h1, l1);
        __nv_bfloat162 hv; hv.x = h0; hv.y = h1;
        __nv_bfloat162 lv; lv.x = l0; lv.y = l1;
        const size_t idx = (size_t)(n0 + n) * K + k0 + kp * 2;
        *(__nv_bfloat162*)(Whi + idx) = hv;
        *(__nv_bfloat162*)(Wlo + idx) = lv;
    }
}

__global__ __launch_bounds__(256)
void prep_kernel(const float* __restrict__ feat, float* __restrict__ featT,
                 const float* __restrict__ fc1_w,
                 __nv_bfloat16* __restrict__ w1h, __nv_bfloat16* __restrict__ w1l,
                 const float* __restrict__ fc2_w,
                 __nv_bfloat16* __restrict__ w2h, __nv_bfloat16* __restrict__ w2l)
{
    __shared__ float tile[32][33];
    const int b = blockIdx.x;
    const int t = threadIdx.x;
    const int WX = (FEAT_W + 31) / 32;     // 5

    if (b < P_FEAT_BLOCKS) {
        const int wx = b % WX;
        const int h  = (b / WX) % FEAT_H;
        const int bz = b / (WX * FEAT_H);
        featT_dev(tile, feat, featT, bz, h, wx * 32, t);
    } else if (b < P_FEAT_BLOCKS + P_W1_BLOCKS) {
        const int idx = b - P_FEAT_BLOCKS;
        const int n0 = (idx & 31) * 32;
        const int k0 = (idx >> 5) * 32;
        transpose_dev<true>(tile, fc1_w, w1h, w1l, KDIM, HID, n0, k0, t);
    } else {
        const int idx = b - P_FEAT_BLOCKS - P_W1_BLOCKS;
        const int n0 = (idx & 31) * 32;
        const int k0 = (idx >> 5) * 32;
        transpose_dev<false>(tile, fc2_w, w2h, w2l, HID, HID, n0, k0, t);
    }
}

// ================= ROI align v4: bin-major output, direct stores =========
__global__ __launch_bounds__(256)
void roi_align4_kernel(const float* __restrict__ featT,
                       const float* __restrict__ boxes,
                       const int*   __restrict__ rbatch,
                       __nv_bfloat16* __restrict__ out_hi,
                       __nv_bfloat16* __restrict__ out_lo)
{
    const int r = blockIdx.x;
    const int t = threadIdx.x;
    const int half = t >> 7;
    const int c0 = (t & 127) * 2;

    __shared__ float sly[14], slx[14];
    __shared__ int   siy0[14], siy1[14], six0c[14], six1c[14];
    __shared__ float box4[4];
    __shared__ int   sb;

    if (t < 4) box4[t] = boxes[r * 4 + t];
    if (t == 4) sb = rbatch[r];
    __syncthreads();

    const float x1 = box4[0] * 0.125f, y1v = box4[1] * 0.125f;
    const float x2 = box4[2] * 0.125f, y2v = box4[3] * 0.125f;
    const float rw = fmaxf(x2 - x1, 1.0f);
    const float rh = fmaxf(y2v - y1v, 1.0f);
    const float bw = rw * (1.0f / 7.0f);
    const float bh = rh * (1.0f / 7.0f);

    if (t < 28) {
        const int p = t % 14;
        const float off = (float)(p >> 1) + ((float)(p & 1) + 0.5f) * 0.5f;
        if (t < 14) {
            float y = y1v + off * bh;
            y = fminf(fmaxf(y, 0.0f), (float)(FEAT_H - 1));
            float y0 = floorf(y);
            int y0i = (int)y0;
            siy0[p] = y0i;
            siy1[p] = min(y0i + 1, FEAT_H - 1);
            sly[p] = y - y0;
        } else {
            float x = x1 + off * bw;
            x = fminf(fmaxf(x, 0.0f), (float)(FEAT_W - 1));
            float x0 = floorf(x);
            int x0i = (int)x0;
            six0c[p] = x0i * FEAT_C;
            six1c[p] = min(x0i + 1, FEAT_W - 1) * FEAT_C;
            slx[p] = x - x0;
        }
    }
    __syncthreads();

    const float* fb = featT + (size_t)sb * (FEAT_H * FEAT_W * FEAT_C) + c0;
    __nv_bfloat16* gh = out_hi + (size_t)r * KDIM + c0;
    __nv_bfloat16* gl = out_lo + (size_t)r * KDIM + c0;

    const int byBeg = half ? 4 : 0;
    const int byEnd = half ? 7 : 4;

    #pragma unroll 1
    for (int by = byBeg; by < byEnd; ++by) {
        float accx[7], accy[7];
        #pragma unroll
        for (int j = 0; j < 7; ++j) { accx[j] = 0.0f; accy[j] = 0.0f; }

        #pragma unroll
        for (int sy = 0; sy < 2; ++sy) {
            const int py = by * 2 + sy;
            const float ly = sly[py];
            const float* r0 = fb + (size_t)(siy0[py] * FEAT_W) * FEAT_C;
            const float* r1 = fb + (size_t)(siy1[py] * FEAT_W) * FEAT_C;
            #pragma unroll
            for (int px = 0; px < 14; ++px) {
                const int x0c = six0c[px], x1c = six1c[px];
                const float lx = slx[px];
                const float2 v00 = *(const float2*)(r0 + x0c);
                const float2 v01 = *(const float2*)(r0 + x1c);
                const float2 v10 = *(const float2*)(r1 + x0c);
                const float2 v11 = *(const float2*)(r1 + x1c);
                const float topx = v00.x + (v01.x - v00.x) * lx;
                const float botx = v10.x + (v11.x - v10.x) * lx;
                const float topy = v00.y + (v01.y - v00.y) * lx;
                const float boty = v10.y + (v11.y - v10.y) * lx;
                accx[px >> 1] += topx + (botx - topx) * ly;
                accy[px >> 1] += topy + (boty - topy) * ly;
            }
        }
        #pragma unroll
        for (int bx = 0; bx < 7; ++bx) {
            const int bin = by * 7 + bx;
            __nv_bfloat16 hx, lxo, hy, lyo;
            split_bf16(accx[bx] * 0.25f, hx, lxo);
            split_bf16(accy[bx] * 0.25f, hy, lyo);
            __nv_bfloat162 hv; hv.x = hx; hv.y = hy;
            __nv_bfloat162 lv; lv.x = lxo; lv.y = lyo;
            *(__nv_bfloat162*)(gh + bin * 256) = hv;
            *(__nv_bfloat162*)(gl + bin * 256) = lv;
        }
    }
}

// ================= split-bf16 mma.sync GEMM, split-K=3 (R10 proven) =====
#define BM 128
#define BN 64
#define BK 32
#define A_STAGE (BM * 64)                          // 8192 B
#define B_STAGE (BN * 64)                          // 4096 B
#define STAGE_BYTES (2 * A_STAGE + 2 * B_STAGE)    // 24576 B
#define GEMM_SMEM (3 * STAGE_BYTES)                // 73728 B

DEV void load_stage(uint32_t st,
                    const __nv_bfloat16* __restrict__ Ah,
                    const __nv_bfloat16* __restrict__ Al,
                    const __nv_bfloat16* __restrict__ Bh,
                    const __nv_bfloat16* __restrict__ Bl,
                    int M, int K, int m0, int n0, int k0, int tid)
{
    const uint32_t sAh = st;
    const uint32_t sAl = st + A_STAGE;
    const uint32_t sBh = st + 2 * A_STAGE;
    const uint32_t sBl = st + 2 * A_STAGE + B_STAGE;

    #pragma unroll
    for (int i = 0; i < 4; ++i) {
        const int q = tid + i * 128;
        const int row = q >> 2, cc = q & 3;
        const int gm = m0 + row;
        const int gmc = gm < M ? gm : (M - 1);
        const uint32_t ssize = gm < M ? 16u : 0u;
        const size_t goff = (size_t)gmc * K + k0 + cc * 8;
        const uint32_t so = swz((uint32_t)row, (uint32_t)cc);
        cp_async16(sAh + so, Ah + goff, ssize);
        cp_async16(sAl + so, Al + goff, ssize);
    }
    #pragma unroll
    for (int i = 0; i < 2; ++i) {
        const int q = tid + i * 128;
        const int row = q >> 2, cc = q & 3;
        const size_t goff = (size_t)(n0 + row) * K + k0 + cc * 8;
        const uint32_t so = swz((uint32_t)row, (uint32_t)cc);
        cp_async16(sBh + so, Bh + goff, 16u);
        cp_async16(sBl + so, Bl + goff, 16u);
    }
    cp_commit();
}

__global__ __launch_bounds__(128, 3)
void gemm_kernel(const __nv_bfloat16* __restrict__ Ah,
                 const __nv_bfloat16* __restrict__ Al,
                 const __nv_bfloat16* __restrict__ Bh,
                 const __nv_bfloat16* __restrict__ Bl,
                 float* __restrict__ part,
                 int M, int K)
{
    extern __shared__ __align__(128) char dsm[];
    const uint32_t base = smem_u32(dsm);

    const int tid = threadIdx.x;
    const int warp_m = tid >> 5;
    const int lane = tid & 31;
    const int m0 = blockIdx.x * BM;
    const int n0 = blockIdx.y * BN;

    const int Ttot = K / BK;
    const int z = blockIdx.z;
    const int t0 = (z * Ttot) / SPLITK;
    const int t1 = ((z + 1) * Ttot) / SPLITK;
    const int nT = t1 - t0;
    float* __restrict__ pz = part + (size_t)z * M * HID;

    float c[2][8][4];
    #pragma unroll
    for (int i = 0; i < 2; ++i)
        #pragma unroll
        for (int j = 0; j < 8; ++j)
            #pragma unroll
            for (int k = 0; k < 4; ++k) c[i][j][k] = 0.0f;

    load_stage(base,               Ah, Al, Bh, Bl, M, K, m0, n0, t0 * BK,       tid);
    load_stage(base + STAGE_BYTES, Ah, Al, Bh, Bl, M, K, m0, n0, (t0 + 1) * BK, tid);

    const int l8 = lane & 7;
    const uint32_t a_row0 = (uint32_t)(warp_m * 32 + l8 + ((lane >> 3) & 1) * 8);
    const uint32_t a_chunk0 = (uint32_t)(lane >> 4);      // + ks*2
    const uint32_t b_row0 = (uint32_t)l8;                  // + j*8
    const uint32_t b_chunk = (uint32_t)(lane >> 3);        // 0..3

    #pragma unroll 1
    for (int lt = 0; lt < nT; ++lt) {
        if (lt + 1 >= nT) cp_wait<0>(); else cp_wait<1>();
        __syncthreads();

        if (lt + 2 < nT)
            load_stage(base + ((lt + 2) % 3) * STAGE_BYTES, Ah, Al, Bh, Bl,
                       M, K, m0, n0, (t0 + lt + 2) * BK, tid);

        const uint32_t st = base + (lt % 3) * STAGE_BYTES;
        const uint32_t sAh = st;
        const uint32_t sAl = st + A_STAGE;
        const uint32_t sBh = st + 2 * A_STAGE;
        const uint32_t sBl = st + 2 * A_STAGE + B_STAGE;

        uint32_t ah[2][2][4], al[2][2][4];
        #pragma unroll
        for (int ma = 0; ma < 2; ++ma) {
            const uint32_t row = a_row0 + ma * 16;
            #pragma unroll
            for (int ks = 0; ks < 2; ++ks) {
                const uint32_t off = swz(row, a_chunk0 + ks * 2);
                ldm_x4(ah[ma][ks], sAh + off);
                ldm_x4(al[ma][ks], sAl + off);
            }
        }

        #pragma unroll
        for (int ch = 0; ch < 2; ++ch) {
            uint32_t bh[4][4], bl[4][4];
            #pragma unroll
            for (int j = 0; j < 4; ++j) {
                const uint32_t off = swz(b_row0 + (ch * 4 + j) * 8, b_chunk);
                ldm_x4(bh[j], sBh + off);
                ldm_x4(bl[j], sBl + off);
            }
            #pragma unroll
            for (int ks = 0; ks < 2; ++ks)
                #pragma unroll
                for (int ma = 0; ma < 2; ++ma)
                    #pragma unroll
                    for (int j = 0; j < 4; ++j) {
                        float* acc = c[ma][ch * 4 + j];
                        mma16816(acc, ah[ma][ks], bh[j] + ks * 2);
                        mma16816(acc, ah[ma][ks], bl[j] + ks * 2);
                        mma16816(acc, al[ma][ks], bh[j] + ks * 2);
                    }
        }
    }

    const int row0 = lane >> 2;
    const int colp = (lane & 3) * 2;
    #pragma unroll
    for (int ma = 0; ma < 2; ++ma) {
        #pragma unroll
        for (int na = 0; na < 8; ++na) {
            const int n = n0 + na * 8 + colp;
            #pragma unroll
            for (int half = 0; half < 2; ++half) {
                const int m = m0 + warp_m * 32 + ma * 16 + row0 + half * 8;
                if (m < M)
                    *(float2*)(pz + (size_t)m * HID + n) =
                        make_float2(c[ma][na][half * 2 + 0], c[ma][na][half * 2 + 1]);
            }
        }
    }
}

// ========== split-K combine + bias + relu (FC1), float4 vectorized ======
__global__ __launch_bounds__(256)
void combine_kernel(const float* __restrict__ part,
                    const float* __restrict__ bias,
                    __nv_bfloat16* __restrict__ outHi,
                    __nv_bfloat16* __restrict__ outLo,
                    int M)
{
    const int idx = blockIdx.x * 256 + threadIdx.x;       // one float4 each
    if (idx * 4 >= M * HID) return;
    const size_t stride = (size_t)M * HID;
    const float4 p0 = *(const float4*)(part + idx * 4);
    const float4 p1 = *(const float4*)(part + stride + idx * 4);
    const float4 p2 = *(const float4*)(part + 2 * stride + idx * 4);
    const int n = (idx * 4) & (HID - 1);
    const float4 bv = *(const float4*)(bias + n);
    const float v0 = fmaxf(p0.x + p1.x + p2.x + bv.x, 0.0f);
    const float v1 = fmaxf(p0.y + p1.y + p2.y + bv.y, 0.0f);
    const float v2 = fmaxf(p0.z + p1.z + p2.z + bv.z, 0.0f);
    const float v3 = fmaxf(p0.w + p1.w + p2.w + bv.w, 0.0f);
    __nv_bfloat16 h0, l0, h1, l1, h2, l2, h3, l3;
    split_bf16(v0, h0, l0); split_bf16(v1, h1, l1);
    split_bf16(v2, h2, l2); split_bf16(v3, h3, l3);
    __nv_bfloat162 hv01; hv01.x = h0; hv01.y = h1;
    __nv_bfloat162 hv23; hv23.x = h2; hv23.y = h3;
    __nv_bfloat162 lv01; lv01.x = l0; lv01.y = l1;
    __nv_bfloat162 lv23; lv23.x = l2; lv23.y = l3;
    *(__nv_bfloat162*)(outHi + idx * 4)     = hv01;
    *(__nv_bfloat162*)(outHi + idx * 4 + 2) = hv23;
    *(__nv_bfloat162*)(outLo + idx * 4)     = lv01;
    *(__nv_bfloat162*)(outLo + idx * 4 + 2) = lv23;
}

// ===== fused heads: split-K combine + bias + relu + GEMV + softmax + decode
__global__ __launch_bounds__(256)
void head_kernel(const float* __restrict__ part,
                 const float* __restrict__ fc2_b,
                 const float* __restrict__ cls_w, const float* __restrict__ cls_b,
                 const float* __restrict__ bbox_w, const float* __restrict__ bbox_b,
                 const float* __restrict__ boxes,
                 float* __restrict__ out)
{
    const int r = blockIdx.x;
    const int t = threadIdx.x;
    float acc[10];
    #pragma unroll
    for (int j = 0; j < 10; ++j) acc[j] = 0.0f;

    const size_t stride = (size_t)NROI * HID;
    const float* p0 = part + (size_t)r * HID;
    #pragma unroll 1
    for (int k = t; k < HID; k += 256) {
        const float hv = fmaxf(p0[k] + p0[stride + k] + p0[2 * stride + k]
                               + fc2_b[k], 0.0f);
        acc[0] += hv * cls_w[k * 2 + 0];
        acc[1] += hv * cls_w[k * 2 + 1];
        #pragma unroll
        for (int j = 0; j < 8; ++j) acc[2 + j] += hv * bbox_w[k * 8 + j];
    }
    #pragma unroll
    for (int off = 16; off > 0; off >>= 1) {
        #pragma unroll
        for (int j = 0; j < 10; ++j)
            acc[j] += __shfl_down_sync(0xFFFFFFFFu, acc[j], off);
    }
    __shared__ float red[8][10];
    const int w = t >> 5, lane = t & 31;
    if (lane == 0) {
        #pragma unroll
        for (int j = 0; j < 10; ++j) red[w][j] = acc[j];
    }
    __syncthreads();
    if (t == 0) {
        float s[10];
        #pragma unroll
        for (int j = 0; j < 10; ++j) {
            float v = 0.0f;
            #pragma unroll
            for (int ww = 0; ww < 8; ++ww) v += red[ww][j];
            s[j] = v;
        }
        s[0] += cls_b[0]; s[1] += cls_b[1];
        #pragma unroll
        for (int j = 0; j < 8; ++j) s[2 + j] += bbox_b[j];

        const float mx = fmaxf(s[0], s[1]);
        const float e0 = expf(s[0] - mx), e1 = expf(s[1] - mx);
        const float inv = 1.0f / (e0 + e1);

        const float bx1 = boxes[r * 4 + 0], by1 = boxes[r * 4 + 1];
        const float bx2 = boxes[r * 4 + 2], by2 = boxes[r * 4 + 3];
        const float pw = bx2 - bx1, ph = by2 - by1;
        const float cx = bx1 + 0.5f * pw, cy = by1 + 0.5f * ph;
        #pragma unroll
        for (int k = 0; k < 2; ++k) {
            const float dx = s[2 + k * 4 + 0] * 0.1f;
            const float dy = s[2 + k * 4 + 1] * 0.1f;
            const float dw = fminf(s[2 + k * 4 + 2] * 0.2f, CLAMP_LOG);
            const float dh = fminf(s[2 + k * 4 + 3] * 0.2f, CLAMP_LOG);
            const float pcx = dx * pw + cx;
            const float pcy = dy * ph + cy;
            const float pww = expf(dw) * pw;
            const float phh = expf(dh) * ph;
            out[r * 10 + k * 4 + 0] = fminf(fmaxf(pcx - 0.5f * pww, 0.0f), IMG_W_);
            out[r * 10 + k * 4 + 1] = fminf(fmaxf(pcy - 0.5f * phh, 0.0f), IMG_H_);
            out[r * 10 + k * 4 + 2] = fminf(fmaxf(pcx + 0.5f * pww, 0.0f), IMG_W_);
            out[r * 10 + k * 4 + 3] = fminf(fmaxf(pcy + 0.5f * phh, 0.0f), IMG_H_);
        }
        out[r * 10 + 8] = e0 * inv;
        out[r * 10 + 9] = e1 * inv;
    }
}

// ================= launch =================
extern "C" void kernel_launch(void* const* d_in, const int* in_sizes, int n_in,
                              void* d_out, int out_size)
{
    const float* features = (const float*)d_in[0];
    const float* boxes    = (const float*)d_in[1];
    const int*   rbatch   = (const int*)  d_in[2];
    const float* fc1_w    = (const float*)d_in[3];
    const float* fc1_b    = (const float*)d_in[4];
    const float* fc2_w    = (const float*)d_in[5];
    const float* fc2_b    = (const float*)d_in[6];
    const float* cls_w    = (const float*)d_in[7];
    const float* cls_b    = (const float*)d_in[8];
    const float* bbox_w   = (const float*)d_in[9];
    const float* bbox_b   = (const float*)d_in[10];
    float* out = (float*)d_out;

    __nv_bfloat16 *fAh, *fAl, *w1h, *w1l, *w2h, *w2l, *h1h, *h1l;
    float *part_p, *featT_p;
    cudaGetSymbolAddress((void**)&featT_p, g_featT);
    cudaGetSymbolAddress((void**)&fAh, g_fA_hi);
    cudaGetSymbolAddress((void**)&fAl, g_fA_lo);
    cudaGetSymbolAddress((void**)&w1h, g_w1t_hi);
    cudaGetSymbolAddress((void**)&w1l, g_w1t_lo);
    cudaGetSymbolAddress((void**)&w2h, g_w2t_hi);
    cudaGetSymbolAddress((void**)&w2l, g_w2t_lo);
    cudaGetSymbolAddress((void**)&h1h, g_h1_hi);
    cudaGetSymbolAddress((void**)&h1l, g_h1_lo);
    cudaGetSymbolAddress((void**)&part_p, g_part);

    cudaFuncSetAttribute(gemm_kernel, cudaFuncAttributeMaxDynamicSharedMemorySize,
                         GEMM_SMEM);

    const int combine_blocks = (NROI * HID / 4 + 255) / 256;

    // fused prep: featT || W1 transpose (bin-major) || W2 transpose
    prep_kernel<<<P_TOTAL, 256>>>(features, featT_p,
                                  fc1_w, w1h, w1l, fc2_w, w2h, w2l);
    roi_align4_kernel<<<NROI, 256>>>(featT_p, boxes, rbatch, fAh, fAl);

    gemm_kernel<<<dim3(8, 16, SPLITK), 128, GEMM_SMEM>>>(fAh, fAl, w1h, w1l, part_p,
                                                         NROI, KDIM);
    combine_kernel<<<combine_blocks, 256>>>(part_p, fc1_b, h1h, h1l, NROI);

    gemm_kernel<<<dim3(8, 16, SPLITK), 128, GEMM_SMEM>>>(h1h, h1l, w2h, w2l, part_p,
                                                         NROI, HID);

    head_kernel<<<NROI, 256>>>(part_p, fc2_b, cls_w, cls_b, bbox_w, bbox_b, boxes, out);
    (void)in_sizes; (void)n_in; (void)out_size;
}